// round 6
// baseline (speedup 1.0000x reference)
#include <cuda_runtime.h>
#include <cuda_fp16.h>
#include <cuda_bf16.h>

#define N_NODES 10000
#define E_EDGES 160000
#define EP (E_EDGES + N_NODES)   // edges + self loops = 170000
#define IN_CH 128
#define EMB 64
#define HEADS 12
#define HD (HEADS * EMB)          // 768
#define NEG_SLOPE 0.2f

// ---- scratch (device globals; no allocation allowed) ----
__device__ float  g_emb[N_NODES * EMB];        // relu(x@We+be)  fp32
__device__ __half g_hh16[N_NODES * HD];        // emb@W, fp16 (only consumer: gather)
__device__ float  g_asrc[N_NODES * HEADS];
__device__ float  g_adst[N_NODES * HEADS];
__device__ int    g_start[N_NODES + 1];        // CSR row offsets (by dst)
__device__ int    g_cursor[N_NODES];           // counts, then scatter cursors
__device__ int    g_csr_src[EP];               // src node per CSR slot

// ---- f32x2 packed-FMA helpers (sm_10x dual-lane FFMA) ----
__device__ __forceinline__ unsigned long long pack2(float lo, float hi) {
    unsigned long long r;
    asm("mov.b64 %0, {%1, %2};" : "=l"(r) : "f"(lo), "f"(hi));
    return r;
}
__device__ __forceinline__ void unpack2(unsigned long long v, float& lo, float& hi) {
    asm("mov.b64 {%0, %1}, %2;" : "=f"(lo), "=f"(hi) : "l"(v));
}
__device__ __forceinline__ void fma2(unsigned long long& d,
                                     unsigned long long a, unsigned long long b) {
    asm("fma.rn.f32x2 %0, %1, %2, %0;" : "+l"(d) : "l"(a), "l"(b));
}

// ---- pass 1: emb = relu(x @ We + be), 16 nodes/block, f32x2 math ----
__global__ void __launch_bounds__(64) k_emb(const float* __restrict__ x,
                                            const float* __restrict__ We,
                                            const float* __restrict__ be) {
    __shared__ float sx[IN_CH][16];
    int n0 = blockIdx.x * 16;
    int t = threadIdx.x;                     // 0..63 = output channel
    for (int idx = t; idx < 16 * IN_CH; idx += 64) {
        int i = idx >> 7, k = idx & 127;
        sx[k][i] = x[(n0 + i) * IN_CH + k];
    }
    __syncthreads();
    float b = be[t];
    unsigned long long acc[8];
    unsigned long long binit = pack2(b, b);
#pragma unroll
    for (int j = 0; j < 8; j++) acc[j] = binit;
    for (int k = 0; k < IN_CH; k++) {
        float wv = We[k * EMB + t];
        unsigned long long w2 = pack2(wv, wv);
#pragma unroll
        for (int j = 0; j < 8; j++)
            fma2(acc[j], *(const unsigned long long*)&sx[k][2 * j], w2);
    }
#pragma unroll
    for (int j = 0; j < 8; j++) {
        float lo, hi;
        unpack2(acc[j], lo, hi);
        g_emb[(n0 + 2 * j) * EMB + t]     = fmaxf(lo, 0.f);
        g_emb[(n0 + 2 * j + 1) * EMB + t] = fmaxf(hi, 0.f);
    }
}

// ---- pass 2: hh = emb @ W (fp16) + fp32 per-head logits, 16 nodes/block ----
__global__ void __launch_bounds__(768) k_hh(const float* __restrict__ W,
                                            const float* __restrict__ att_src,
                                            const float* __restrict__ att_dst) {
    __shared__ float se[EMB][16];
    __shared__ float ssrc[16][HEADS];
    __shared__ float sdst[16][HEADS];
    int n0 = blockIdx.x * 16;
    int t = threadIdx.x;                     // 0..767
    for (int idx = t; idx < 16 * EMB; idx += 768) {
        int i = idx >> 6, k = idx & 63;
        se[k][i] = g_emb[(n0 + i) * EMB + k];
    }
    if (t < 16 * HEADS) {
        ((float*)ssrc)[t] = 0.f;
        ((float*)sdst)[t] = 0.f;
    }
    __syncthreads();
    unsigned long long acc[8];
#pragma unroll
    for (int j = 0; j < 8; j++) acc[j] = 0ull;
    for (int k = 0; k < EMB; k++) {
        float wv = W[k * HD + t];
        unsigned long long w2 = pack2(wv, wv);
#pragma unroll
        for (int j = 0; j < 8; j++)
            fma2(acc[j], *(const unsigned long long*)&se[k][2 * j], w2);
    }
    float av[16];
#pragma unroll
    for (int j = 0; j < 8; j++) unpack2(acc[j], av[2 * j], av[2 * j + 1]);

    float as = att_src[t], ad = att_dst[t];
    int h = t >> 6;                          // constant within each warp
#pragma unroll
    for (int i = 0; i < 16; i++) {
        g_hh16[(size_t)(n0 + i) * HD + t] = __float2half_rn(av[i]);
        float ps = av[i] * as;
        float pd = av[i] * ad;
#pragma unroll
        for (int off = 16; off; off >>= 1) {
            ps += __shfl_down_sync(0xffffffffu, ps, off);
            pd += __shfl_down_sync(0xffffffffu, pd, off);
        }
        if ((t & 31) == 0) {
            atomicAdd(&ssrc[i][h], ps);
            atomicAdd(&sdst[i][h], pd);
        }
    }
    __syncthreads();
    if (t < 16 * HEADS) {
        int i = t / HEADS, hh_ = t % HEADS;
        g_asrc[(n0 + i) * HEADS + hh_] = ssrc[i][hh_];
        g_adst[(n0 + i) * HEADS + hh_] = sdst[i][hh_];
    }
}

// ---- CSR build: zero counts ----
__global__ void k_zero() {
    int idx = blockIdx.x * blockDim.x + threadIdx.x;
    if (idx < N_NODES) g_cursor[idx] = 0;
}

// ---- CSR build: histogram of in-degrees (incl. self loops) ----
__global__ void k_hist(const int* __restrict__ ei) {
    int e = blockIdx.x * blockDim.x + threadIdx.x;
    if (e >= EP) return;
    int d = (e < E_EDGES) ? ei[E_EDGES + e] : (e - E_EDGES);
    atomicAdd(&g_cursor[d], 1);
}

// ---- CSR build: exclusive scan (single block, 1024 thr x 10 elems) ----
__global__ void __launch_bounds__(1024) k_scan() {
    __shared__ int ssum[1024];
    int t = threadIdx.x;
    int base = t * 10;
    int local[10];
    int s = 0;
#pragma unroll
    for (int i = 0; i < 10; i++) {
        int idx = base + i;
        int c = (idx < N_NODES) ? g_cursor[idx] : 0;
        local[i] = s;
        s += c;
    }
    ssum[t] = s;
    __syncthreads();
    for (int off = 1; off < 1024; off <<= 1) {
        int v = (t >= off) ? ssum[t - off] : 0;
        __syncthreads();
        ssum[t] += v;
        __syncthreads();
    }
    int offset = (t > 0) ? ssum[t - 1] : 0;
#pragma unroll
    for (int i = 0; i < 10; i++) {
        int idx = base + i;
        if (idx < N_NODES) {
            g_start[idx] = offset + local[i];
            g_cursor[idx] = offset + local[i];
        }
    }
    if (t == 1023) g_start[N_NODES] = ssum[1023];
}

// ---- CSR build: scatter sources into per-dst segments ----
__global__ void k_scatter(const int* __restrict__ ei) {
    int e = blockIdx.x * blockDim.x + threadIdx.x;
    if (e >= EP) return;
    int s, d;
    if (e < E_EDGES) { s = ei[e]; d = ei[E_EDGES + e]; }
    else             { s = d = e - E_EDGES; }
    int pos = atomicAdd(&g_cursor[d], 1);
    g_csr_src[pos] = s;
}

// ---- pass 3: fused softmax + aggregate + epilogue, 1 warp per dst node ----
// out[d][j] = relu(emb[d][j] + bias[j] + (1/12)*sum_h (sum_e exp_eh*hh[s][h][j]) / denom[h])
__global__ void __launch_bounds__(256) k_node(const float* __restrict__ bias,
                                              float* __restrict__ out) {
    int n = blockIdx.x * 8 + (threadIdx.x >> 5);
    int lane = threadIdx.x & 31;
    if (n >= N_NODES) return;

    float ad = (lane < HEADS) ? g_adst[n * HEADS + lane] : 0.f;
    int e   = g_start[n];
    int end = g_start[n + 1];

    float acc[2 * HEADS];
#pragma unroll
    for (int q = 0; q < 2 * HEADS; q++) acc[q] = 0.f;
    float den = 0.f;

    // prefetch first edge
    int s = (lane == 0 && e < end) ? g_csr_src[e] : 0;
    s = __shfl_sync(0xffffffffu, s, 0);
    float a = (lane < HEADS && e < end) ? g_asrc[s * HEADS + lane] : 0.f;

    const __half2* __restrict__ hbase = (const __half2*)g_hh16;
    while (e < end) {
        int e2 = e + 1;
        int s2 = (lane == 0 && e2 < end) ? g_csr_src[e2] : 0;
        s2 = __shfl_sync(0xffffffffu, s2, 0);
        float a2 = (lane < HEADS && e2 < end) ? g_asrc[s2 * HEADS + lane] : 0.f;

        float v = a + ad;
        v = v > 0.f ? v : NEG_SLOPE * v;
        float ex = __expf(v);
        den += ex;                           // meaningful only for lane<12
        const __half2* hrow = hbase + (size_t)s * (HD / 2);
#pragma unroll
        for (int h = 0; h < HEADS; h++) {
            float w = __shfl_sync(0xffffffffu, ex, h);
            float2 f = __half22float2(hrow[h * 32 + lane]);
            acc[2 * h]     += w * f.x;
            acc[2 * h + 1] += w * f.y;
        }
        s = s2; a = a2; e = e2;
    }

    float id = (lane < HEADS) ? 1.f / (den + 1e-16f) : 0.f;
    float sum0 = 0.f, sum1 = 0.f;
#pragma unroll
    for (int h = 0; h < HEADS; h++) {
        float dh = __shfl_sync(0xffffffffu, id, h);
        sum0 += acc[2 * h] * dh;
        sum1 += acc[2 * h + 1] * dh;
    }
    int j0 = 2 * lane, j1 = 2 * lane + 1;
    const float* eb = g_emb + (size_t)n * EMB;
    out[n * EMB + j0] = fmaxf(eb[j0] + sum0 * (1.f / HEADS) + bias[j0], 0.f);
    out[n * EMB + j1] = fmaxf(eb[j1] + sum1 * (1.f / HEADS) + bias[j1], 0.f);
}

extern "C" void kernel_launch(void* const* d_in, const int* in_sizes, int n_in,
                              void* d_out, int out_size) {
    const float* x    = (const float*)d_in[0];
    const int*   ei   = (const int*)d_in[1];
    const float* We   = (const float*)d_in[2];
    const float* be   = (const float*)d_in[3];
    const float* W    = (const float*)d_in[4];
    const float* asrc = (const float*)d_in[5];
    const float* adst = (const float*)d_in[6];
    const float* bias = (const float*)d_in[7];
    float* out = (float*)d_out;

    k_emb<<<N_NODES / 16, 64>>>(x, We, be);
    k_zero<<<(N_NODES + 255) / 256, 256>>>();
    k_hist<<<(EP + 255) / 256, 256>>>(ei);
    k_scan<<<1, 1024>>>();
    k_scatter<<<(EP + 255) / 256, 256>>>(ei);
    k_hh<<<N_NODES / 16, 768>>>(W, asrc, adst);
    k_node<<<(N_NODES + 7) / 8, 256>>>(bias, out);
}

// round 8
// speedup vs baseline: 1.4654x; 1.4654x over previous
#include <cuda_runtime.h>
#include <cuda_fp16.h>
#include <cuda_bf16.h>

#define N_NODES 10000
#define E_EDGES 160000
#define EP (E_EDGES + N_NODES)   // 170000 (even -> exact warps in k_agg)
#define IN_CH 128
#define EMB 64
#define HEADS 12
#define HD (HEADS * EMB)          // 768
#define NEG_SLOPE 0.2f

// ---- scratch (device globals; no allocation allowed) ----
__device__ float  g_emb[N_NODES * EMB];
__device__ __half g_hh16[N_NODES * HD];        // fp16, only consumer: k_agg gather
__device__ float  g_asrc[N_NODES * HEADS];
__device__ float  g_adst[N_NODES * HEADS];
__device__ float  g_denom[N_NODES * HEADS];
__device__ float  g_invden[N_NODES * HEADS];
__device__ float  g_eexp[EP * HEADS];
__device__ float  g_agg[N_NODES * EMB];

// ---- f32x2 packed-FMA helpers ----
__device__ __forceinline__ unsigned long long pack2(float lo, float hi) {
    unsigned long long r;
    asm("mov.b64 %0, {%1, %2};" : "=l"(r) : "f"(lo), "f"(hi));
    return r;
}
__device__ __forceinline__ void unpack2(unsigned long long v, float& lo, float& hi) {
    asm("mov.b64 {%0, %1}, %2;" : "=f"(lo), "=f"(hi) : "l"(v));
}
__device__ __forceinline__ void fma2(unsigned long long& d,
                                     unsigned long long a, unsigned long long b) {
    asm("fma.rn.f32x2 %0, %1, %2, %0;" : "+l"(d) : "l"(a), "l"(b));
}

// ---- pass 1: emb = relu(x @ We + be), 16 nodes/block, f32x2 ----
__global__ void __launch_bounds__(64) k_emb(const float* __restrict__ x,
                                            const float* __restrict__ We,
                                            const float* __restrict__ be) {
    __shared__ float sx[IN_CH][16];
    int n0 = blockIdx.x * 16;
    int t = threadIdx.x;
    for (int idx = t; idx < 16 * IN_CH; idx += 64) {
        int i = idx >> 7, k = idx & 127;
        sx[k][i] = x[(n0 + i) * IN_CH + k];
    }
    __syncthreads();
    float b = be[t];
    unsigned long long acc[8];
    unsigned long long binit = pack2(b, b);
#pragma unroll
    for (int j = 0; j < 8; j++) acc[j] = binit;
    for (int k = 0; k < IN_CH; k++) {
        float wv = We[k * EMB + t];
        unsigned long long w2 = pack2(wv, wv);
#pragma unroll
        for (int j = 0; j < 8; j++)
            fma2(acc[j], *(const unsigned long long*)&sx[k][2 * j], w2);
    }
#pragma unroll
    for (int j = 0; j < 8; j++) {
        float lo, hi;
        unpack2(acc[j], lo, hi);
        g_emb[(n0 + 2 * j) * EMB + t]     = fmaxf(lo, 0.f);
        g_emb[(n0 + 2 * j + 1) * EMB + t] = fmaxf(hi, 0.f);
    }
}

// ---- pass 2: hh = emb @ W (fp16 out) + fp32 logits, 16 nodes/block ----
__global__ void __launch_bounds__(768) k_hh(const float* __restrict__ W,
                                            const float* __restrict__ att_src,
                                            const float* __restrict__ att_dst) {
    __shared__ float se[EMB][16];
    __shared__ float ssrc[16][HEADS];
    __shared__ float sdst[16][HEADS];
    int n0 = blockIdx.x * 16;
    int t = threadIdx.x;
    for (int idx = t; idx < 16 * EMB; idx += 768) {
        int i = idx >> 6, k = idx & 63;
        se[k][i] = g_emb[(n0 + i) * EMB + k];
    }
    if (t < 16 * HEADS) {
        ((float*)ssrc)[t] = 0.f;
        ((float*)sdst)[t] = 0.f;
    }
    __syncthreads();
    unsigned long long acc[8];
#pragma unroll
    for (int j = 0; j < 8; j++) acc[j] = 0ull;
    for (int k = 0; k < EMB; k++) {
        float wv = W[k * HD + t];
        unsigned long long w2 = pack2(wv, wv);
#pragma unroll
        for (int j = 0; j < 8; j++)
            fma2(acc[j], *(const unsigned long long*)&se[k][2 * j], w2);
    }
    float av[16];
#pragma unroll
    for (int j = 0; j < 8; j++) unpack2(acc[j], av[2 * j], av[2 * j + 1]);

    float as = att_src[t], ad = att_dst[t];
    int h = t >> 6;
#pragma unroll
    for (int i = 0; i < 16; i++) {
        g_hh16[(size_t)(n0 + i) * HD + t] = __float2half_rn(av[i]);
        float ps = av[i] * as;
        float pd = av[i] * ad;
#pragma unroll
        for (int off = 16; off; off >>= 1) {
            ps += __shfl_down_sync(0xffffffffu, ps, off);
            pd += __shfl_down_sync(0xffffffffu, pd, off);
        }
        if ((t & 31) == 0) {
            atomicAdd(&ssrc[i][h], ps);
            atomicAdd(&sdst[i][h], pd);
        }
    }
    __syncthreads();
    if (t < 16 * HEADS) {
        int i = t / HEADS, hh_ = t % HEADS;
        g_asrc[(n0 + i) * HEADS + hh_] = ssrc[i][hh_];
        g_adst[(n0 + i) * HEADS + hh_] = sdst[i][hh_];
    }
}

// ---- init scratch each launch (graph replays!) ----
__global__ void k_init() {
    int idx = blockIdx.x * blockDim.x + threadIdx.x;
    if (idx < N_NODES * EMB) g_agg[idx] = 0.f;
    if (idx < N_NODES * HEADS) g_denom[idx] = 0.f;
}

// ---- pass 3: thread per (edge, head): exp(leaky(logit)), atomic denom ----
__global__ void k_sum(const int* __restrict__ ei) {
    int idx = blockIdx.x * blockDim.x + threadIdx.x;
    if (idx >= EP * HEADS) return;
    int e = idx / HEADS, h = idx - e * HEADS;
    int s, d;
    if (e < E_EDGES) { s = ei[e]; d = ei[E_EDGES + e]; }
    else             { s = d = e - E_EDGES; }
    float v = g_asrc[s * HEADS + h] + g_adst[d * HEADS + h];
    v = v > 0.f ? v : NEG_SLOPE * v;
    float ex = __expf(v);
    g_eexp[idx] = ex;
    atomicAdd(&g_denom[d * HEADS + h], ex);
}

// ---- pass 3b: reciprocal of denominators ----
__global__ void k_inv() {
    int idx = blockIdx.x * blockDim.x + threadIdx.x;
    if (idx < N_NODES * HEADS)
        g_invden[idx] = 1.f / (g_denom[idx] + 1e-16f);
}

// ---- pass 4: weighted aggregate. 2 edges/warp, 16 lanes/edge,
//      4 channels/lane, float4 atomics (RED.E.128). ----
__global__ void __launch_bounds__(256) k_agg(const int* __restrict__ ei) {
    int w = (blockIdx.x * blockDim.x + threadIdx.x) >> 5;   // warp id = edge pair
    int lane = threadIdx.x & 31;
    int half = lane >> 4;                                   // which edge of the pair
    int l = lane & 15;                                      // lane within edge group
    int e = w * 2 + half;                                   // EP even: always valid
    int s, d;
    if (e < E_EDGES) { s = ei[e]; d = ei[E_EDGES + e]; }
    else             { s = d = e - E_EDGES; }

    float wl = 0.f;
    if (l < HEADS)
        wl = g_eexp[e * HEADS + l] * g_invden[d * HEADS + l];

    const float2* __restrict__ hrow = (const float2*)(g_hh16 + (size_t)s * HD);
    float a0 = 0.f, a1 = 0.f, a2 = 0.f, a3 = 0.f;
#pragma unroll
    for (int h = 0; h < HEADS; h++) {
        float wv = __shfl_sync(0xffffffffu, wl, h, 16);     // within 16-lane segment
        float2 p = hrow[h * 16 + l];                        // 2 x half2 = 4 channels
        float2 f0 = __half22float2(*(const __half2*)&p.x);
        float2 f1 = __half22float2(*(const __half2*)&p.y);
        a0 += wv * f0.x; a1 += wv * f0.y;
        a2 += wv * f1.x; a3 += wv * f1.y;
    }
    atomicAdd((float4*)&g_agg[d * EMB + 4 * l], make_float4(a0, a1, a2, a3));
}

// ---- pass 5: out = relu(emb + mean_heads(agg) + bias) ----
__global__ void k_final(const float* __restrict__ bias, float* __restrict__ out) {
    int idx = blockIdx.x * blockDim.x + threadIdx.x;
    if (idx >= N_NODES * EMB) return;
    int c = idx & 63;
    out[idx] = fmaxf(g_emb[idx] + g_agg[idx] * (1.f / HEADS) + bias[c], 0.f);
}

extern "C" void kernel_launch(void* const* d_in, const int* in_sizes, int n_in,
                              void* d_out, int out_size) {
    const float* x    = (const float*)d_in[0];
    const int*   ei   = (const int*)d_in[1];
    const float* We   = (const float*)d_in[2];
    const float* be   = (const float*)d_in[3];
    const float* W    = (const float*)d_in[4];
    const float* asrc = (const float*)d_in[5];
    const float* adst = (const float*)d_in[6];
    const float* bias = (const float*)d_in[7];
    float* out = (float*)d_out;

    k_emb<<<N_NODES / 16, 64>>>(x, We, be);
    k_init<<<(N_NODES * EMB + 255) / 256, 256>>>();
    k_hh<<<N_NODES / 16, 768>>>(W, asrc, adst);
    k_sum<<<(EP * HEADS + 255) / 256, 256>>>(ei);
    k_inv<<<(N_NODES * HEADS + 255) / 256, 256>>>();
    k_agg<<<(EP / 2 * 32 + 255) / 256, 256>>>(ei);
    k_final<<<(N_NODES * EMB + 255) / 256, 256>>>(bias, out);
}